// round 13
// baseline (speedup 1.0000x reference)
#include <cuda_runtime.h>
#include <cuda_bf16.h>

// Scratch (device globals; zero-initialized at module load).
// g_sV: plain stores; stale entries only for rows with U<=0 (never read).
// g_pP/g_pPh: atomic accumulators, re-zeroed each run by epilogue blocks.
__device__ float g_sV[8192];
__device__ float g_pP[8192];
__device__ float g_pPh[8192];
__device__ unsigned g_done  = 0;
__device__ unsigned g_done2 = 0;

#define EPI_BLOCKS 64

// Single-launch fused kernel using the R4 matvec layout (measured 5.6TB/s):
//   grid 768 x 256 threads, launch_bounds(256) (4 CTAs/SM resident + 2nd wave)
//   blocks [0,512):   W block  — 8 contiguous rows (b*8+warp), warp per row,
//                     full 4096 cols, MLP~8; rows with U<=0 skipped (-16MB).
//   blocks [512,768): P/Ph block — 128 rows x 1024 cols, 256 thr x float4,
//                     8-row load batches (MLP~10), atomicAdd partials.
// Blocks 0..63 (W blocks — finish early) also run the epilogue: rank
// precompute hidden under P-block traffic, spin on done counter, then
// L2-hot elementwise writes. No second kernel launch.
__global__ __launch_bounds__(256)
void fused_kernel(const float* __restrict__ W,  const float* __restrict__ Vn,
                  const float* __restrict__ P,  const float* __restrict__ Ph,
                  const float* __restrict__ pi, const float* __restrict__ C,
                  const float* __restrict__ L,  const float* __restrict__ U,
                  const float* __restrict__ alpha, float* __restrict__ out,
                  int N, int Nnext, int K, int Prows, int G) {
    const int tid  = threadIdx.x;
    const int b    = blockIdx.x;
    const int lane = tid & 31;
    const int warp = tid >> 5;           // [0,8)

    const int nWBlocks = N / 8;          // 512

    if (b < nWBlocks) {
        // ---- W block: 8 contiguous rows, warp per row ----
        const int row = b * 8 + warp;

        if (__ldg(U + row) > 0.0f) {     // sV unused when U <= 0
            const float4* wr = reinterpret_cast<const float4*>(W + (size_t)row * Nnext) + lane;
            const float4* vv = reinterpret_cast<const float4*>(Vn) + lane;
            const int nBatch = Nnext / (32 * 4 * 4);      // 4096/512 = 8

            float acc = 0.0f;
            #pragma unroll 1
            for (int it = 0; it < nBatch; ++it) {
                float4 w0 = __ldg(wr + 0 * 32);
                float4 w1 = __ldg(wr + 1 * 32);
                float4 w2 = __ldg(wr + 2 * 32);
                float4 w3 = __ldg(wr + 3 * 32);
                float4 v0 = __ldg(vv + 0 * 32);
                float4 v1 = __ldg(vv + 1 * 32);
                float4 v2 = __ldg(vv + 2 * 32);
                float4 v3 = __ldg(vv + 3 * 32);
                acc = fmaf(w0.x, v0.x, acc); acc = fmaf(w0.y, v0.y, acc);
                acc = fmaf(w0.z, v0.z, acc); acc = fmaf(w0.w, v0.w, acc);
                acc = fmaf(w1.x, v1.x, acc); acc = fmaf(w1.y, v1.y, acc);
                acc = fmaf(w1.z, v1.z, acc); acc = fmaf(w1.w, v1.w, acc);
                acc = fmaf(w2.x, v2.x, acc); acc = fmaf(w2.y, v2.y, acc);
                acc = fmaf(w2.z, v2.z, acc); acc = fmaf(w2.w, v2.w, acc);
                acc = fmaf(w3.x, v3.x, acc); acc = fmaf(w3.y, v3.y, acc);
                acc = fmaf(w3.z, v3.z, acc); acc = fmaf(w3.w, v3.w, acc);
                wr += 4 * 32;
                vv += 4 * 32;
            }
            #pragma unroll
            for (int o = 16; o > 0; o >>= 1)
                acc += __shfl_down_sync(0xFFFFFFFFu, acc, o);
            if (lane == 0) g_sV[row] = acc;
        }
    } else {
        // ---- P / P_hat block: 128 rows x 1024 cols ----
        int pb = b - nWBlocks;                       // [0, 256)
        const int nPBlocks = (Prows / 128) * (K / 1024);   // 128
        const float* mat; float* o_;
        if (pb < nPBlocks) { mat = P;  o_ = g_pP;  }
        else               { mat = Ph; o_ = g_pPh; pb -= nPBlocks; }

        const int pColTiles = K / 1024;              // 2
        const int col = (pb % pColTiles) * 1024 + tid * 4;
        const int r0  = (pb / pColTiles) * 128;

        const float4* m  = reinterpret_cast<const float4*>(mat + (size_t)r0 * K + col);
        const float4* p4 = reinterpret_cast<const float4*>(pi + r0);
        const size_t  s4 = (size_t)K / 4;

        float4 acc = make_float4(0.f, 0.f, 0.f, 0.f);
        #pragma unroll 1
        for (int rr = 0; rr < 128; rr += 8) {
            float4 w0 = __ldg(m + 0 * s4);
            float4 w1 = __ldg(m + 1 * s4);
            float4 w2 = __ldg(m + 2 * s4);
            float4 w3 = __ldg(m + 3 * s4);
            float4 w4 = __ldg(m + 4 * s4);
            float4 w5 = __ldg(m + 5 * s4);
            float4 w6 = __ldg(m + 6 * s4);
            float4 w7 = __ldg(m + 7 * s4);
            float4 pa = __ldg(p4 + 0);
            float4 pb2 = __ldg(p4 + 1);

            acc.x = fmaf(pa.x, w0.x, acc.x); acc.y = fmaf(pa.x, w0.y, acc.y);
            acc.z = fmaf(pa.x, w0.z, acc.z); acc.w = fmaf(pa.x, w0.w, acc.w);
            acc.x = fmaf(pa.y, w1.x, acc.x); acc.y = fmaf(pa.y, w1.y, acc.y);
            acc.z = fmaf(pa.y, w1.z, acc.z); acc.w = fmaf(pa.y, w1.w, acc.w);
            acc.x = fmaf(pa.z, w2.x, acc.x); acc.y = fmaf(pa.z, w2.y, acc.y);
            acc.z = fmaf(pa.z, w2.z, acc.z); acc.w = fmaf(pa.z, w2.w, acc.w);
            acc.x = fmaf(pa.w, w3.x, acc.x); acc.y = fmaf(pa.w, w3.y, acc.y);
            acc.z = fmaf(pa.w, w3.z, acc.z); acc.w = fmaf(pa.w, w3.w, acc.w);
            acc.x = fmaf(pb2.x, w4.x, acc.x); acc.y = fmaf(pb2.x, w4.y, acc.y);
            acc.z = fmaf(pb2.x, w4.z, acc.z); acc.w = fmaf(pb2.x, w4.w, acc.w);
            acc.x = fmaf(pb2.y, w5.x, acc.x); acc.y = fmaf(pb2.y, w5.y, acc.y);
            acc.z = fmaf(pb2.y, w5.z, acc.z); acc.w = fmaf(pb2.y, w5.w, acc.w);
            acc.x = fmaf(pb2.z, w6.x, acc.x); acc.y = fmaf(pb2.z, w6.y, acc.y);
            acc.z = fmaf(pb2.z, w6.z, acc.z); acc.w = fmaf(pb2.z, w6.w, acc.w);
            acc.x = fmaf(pb2.w, w7.x, acc.x); acc.y = fmaf(pb2.w, w7.y, acc.y);
            acc.z = fmaf(pb2.w, w7.z, acc.z); acc.w = fmaf(pb2.w, w7.w, acc.w);

            m  += 8 * s4;
            p4 += 2;
        }
        atomicAdd(&o_[col + 0], acc.x);
        atomicAdd(&o_[col + 1], acc.y);
        atomicAdd(&o_[col + 2], acc.z);
        atomicAdd(&o_[col + 3], acc.w);
    }

    // ---------------- signal matvec completion (race-safe) ----------------
    __syncthreads();               // all warps of this block done with stores
    __threadfence();
    if (tid == 0) atomicAdd(&g_done, 1u);
    if (b >= EPI_BLOCKS) return;

    // ======== epilogue blocks (b in [0, EPI_BLOCKS)) — light W blocks ======
    // Rank precompute (depends only on L/U) — runs while P blocks still
    // stream the bulk of the traffic.
    const int sliceLen   = (N + EPI_BLOCKS - 1) / EPI_BLOCKS;   // 64 @ N=4096
    const int sliceStart = b * sliceLen;

    int pre = 0;
    for (int i = tid; i < sliceStart; i += 256) {
        float li = __ldg(L + i), ui = __ldg(U + i);
        pre += (li < 0.0f && ui > 0.0f);
    }
    #pragma unroll
    for (int o = 16; o > 0; o >>= 1)
        pre += __shfl_down_sync(0xFFFFFFFFu, pre, o);
    __shared__ int wsum[8];
    __shared__ int wcnt[8];
    if (lane == 0) wsum[warp] = pre;
    if (tid < 8) wcnt[tid] = 0;
    __syncthreads();

    const int n = sliceStart + tid;          // one neuron per thread (tid<64)
    float l = 0.f, u = 0.f, c = 0.f;
    bool un = false;
    const bool active = (tid < sliceLen) && (n < N);
    if (active) {
        l = __ldg(L + n); u = __ldg(U + n); c = __ldg(C + n);
        un = (l < 0.0f) && (u > 0.0f);
    }
    unsigned bm = __ballot_sync(0xFFFFFFFFu, un);
    int before = __popc(bm & ((1u << lane) - 1u));
    if (lane == 0) wcnt[warp] = __popc(bm);
    __syncthreads();

    int prefix = 0;
    #pragma unroll
    for (int w = 0; w < 8; ++w) prefix += wsum[w];
    int woff = 0, totalCnt = 0;
    #pragma unroll
    for (int w = 0; w < 8; ++w) {
        woff     += (w < warp) ? wcnt[w] : 0;
        totalCnt += wcnt[w];
    }
    const int k = prefix + woff + before;
    float a_k = 0.0f;
    if (active && un && k < K) a_k = __ldg(alpha + k);

    // ---------------- wait for ALL blocks ----------------
    if (tid == 0) {
        while (atomicAdd(&g_done, 0u) < (unsigned)G) __nanosleep(32);
    }
    __syncthreads();
    __threadfence();

    // ---------------- elementwise epilogue (L2-hot) ----------------
    if (active) {
        float val;
        if (un) {
            if (k < K) {
                float vhat = g_sV[n] - g_pPh[k];
                float rp   = fmaxf(vhat, 0.0f);
                float rn   = fmaxf(-vhat, 0.0f);
                val = rp * u / (u - l) - c - a_k * rn - g_pP[k];
            } else {
                val = 0.0f;
            }
        } else if (u <= 0.0f) {
            val = -c;                  // stably deactivated (sV never needed)
        } else if (l >= 0.0f) {
            val = g_sV[n] - c;         // stably activated
        } else {
            val = 0.0f;
        }
        out[n] = val;
    }

    // ---------------- reset scratch for next graph replay ----------------
    __syncthreads();
    const int zEnd = (b == EPI_BLOCKS - 1) ? K : (prefix + totalCnt);
    for (int i = prefix + tid; i < zEnd; i += 256) {
        g_pP[i]  = 0.0f;
        g_pPh[i] = 0.0f;
    }
    __threadfence();
    if (tid == 0) {
        unsigned d2 = atomicAdd(&g_done2, 1u);
        if (d2 == EPI_BLOCKS - 1) {   // very last epilogue block resets counters
            g_done  = 0;
            g_done2 = 0;
            __threadfence();
        }
    }
}

extern "C" void kernel_launch(void* const* d_in, const int* in_sizes, int n_in,
                              void* d_out, int out_size) {
    const float* Vn    = (const float*)d_in[0];   // [N_NEXT]
    const float* W     = (const float*)d_in[1];   // [N_NEXT, N]
    const float* C     = (const float*)d_in[2];   // [N]
    const float* L     = (const float*)d_in[3];   // [N]
    const float* U     = (const float*)d_in[4];   // [N]
    const float* P     = (const float*)d_in[5];   // [P_ROWS, K]
    const float* Ph    = (const float*)d_in[6];   // [P_ROWS, K]
    const float* pi    = (const float*)d_in[7];   // [P_ROWS]
    const float* alpha = (const float*)d_in[8];   // [K]
    float* out = (float*)d_out;

    const int Nnext = in_sizes[0];
    const int N     = in_sizes[2];
    const int Prows = in_sizes[7];
    const int K     = in_sizes[8];

    // R4 layout: 512 W blocks + 2 * 128 P blocks = 768
    const int G = N / 8 + 2 * (Prows / 128) * (K / 1024);

    fused_kernel<<<G, 256>>>(W, Vn, P, Ph, pi, C, L, U, alpha, out,
                             N, Nnext, K, Prows, G);
}

// round 14
// speedup vs baseline: 1.3117x; 1.3117x over previous
#include <cuda_runtime.h>
#include <cuda_bf16.h>

// Scratch (device globals; zero-initialized at module load).
// g_sV: plain stores; stale entries only for rows with U<=0 (never read).
// g_pP/g_pPh: atomic accumulators, re-zeroed each run by epilogue blocks.
__device__ float g_sV[8192];
__device__ float g_pP[8192];
__device__ float g_pPh[8192];
__device__ unsigned g_done  = 0;
__device__ unsigned g_done2 = 0;

#define EPI_BLOCKS 64

// Single-launch fused kernel, R4 heterogeneous layout:
//   grid 768 x 256 threads, __launch_bounds__(256, 4) -> 64-reg budget so all
//   batched loads stay in flight (R13 regressed because ptxas chose 32 regs).
//   blocks [0,512):   W block  — 8 contiguous rows (b*8+warp), warp per row,
//                     full 4096 cols, MLP~8; rows with U<=0 skipped (-16MB).
//   blocks [512,768): P/Ph block — 128 rows x 1024 cols, 256 thr x float4,
//                     8-row load batches (MLP~10), atomicAdd partials.
// Blocks 0..63 (W blocks — finish early) also run the epilogue: rank
// precompute hidden under P-block traffic, spin on done counter, then
// L2-hot elementwise writes. No second kernel launch.
__global__ __launch_bounds__(256, 4)
void fused_kernel(const float* __restrict__ W,  const float* __restrict__ Vn,
                  const float* __restrict__ P,  const float* __restrict__ Ph,
                  const float* __restrict__ pi, const float* __restrict__ C,
                  const float* __restrict__ L,  const float* __restrict__ U,
                  const float* __restrict__ alpha, float* __restrict__ out,
                  int N, int Nnext, int K, int Prows, int G) {
    const int tid  = threadIdx.x;
    const int b    = blockIdx.x;
    const int lane = tid & 31;
    const int warp = tid >> 5;           // [0,8)

    const int nWBlocks = N / 8;          // 512

    if (b < nWBlocks) {
        // ---- W block: 8 contiguous rows, warp per row ----
        const int row = b * 8 + warp;

        if (__ldg(U + row) > 0.0f) {     // sV unused when U <= 0
            const float4* wr = reinterpret_cast<const float4*>(W + (size_t)row * Nnext) + lane;
            const float4* vv = reinterpret_cast<const float4*>(Vn) + lane;
            const int nBatch = Nnext / (32 * 4 * 4);      // 4096/512 = 8

            float acc = 0.0f;
            #pragma unroll 1
            for (int it = 0; it < nBatch; ++it) {
                float4 w0 = __ldg(wr + 0 * 32);
                float4 w1 = __ldg(wr + 1 * 32);
                float4 w2 = __ldg(wr + 2 * 32);
                float4 w3 = __ldg(wr + 3 * 32);
                float4 v0 = __ldg(vv + 0 * 32);
                float4 v1 = __ldg(vv + 1 * 32);
                float4 v2 = __ldg(vv + 2 * 32);
                float4 v3 = __ldg(vv + 3 * 32);
                acc = fmaf(w0.x, v0.x, acc); acc = fmaf(w0.y, v0.y, acc);
                acc = fmaf(w0.z, v0.z, acc); acc = fmaf(w0.w, v0.w, acc);
                acc = fmaf(w1.x, v1.x, acc); acc = fmaf(w1.y, v1.y, acc);
                acc = fmaf(w1.z, v1.z, acc); acc = fmaf(w1.w, v1.w, acc);
                acc = fmaf(w2.x, v2.x, acc); acc = fmaf(w2.y, v2.y, acc);
                acc = fmaf(w2.z, v2.z, acc); acc = fmaf(w2.w, v2.w, acc);
                acc = fmaf(w3.x, v3.x, acc); acc = fmaf(w3.y, v3.y, acc);
                acc = fmaf(w3.z, v3.z, acc); acc = fmaf(w3.w, v3.w, acc);
                wr += 4 * 32;
                vv += 4 * 32;
            }
            #pragma unroll
            for (int o = 16; o > 0; o >>= 1)
                acc += __shfl_down_sync(0xFFFFFFFFu, acc, o);
            if (lane == 0) g_sV[row] = acc;
        }
    } else {
        // ---- P / P_hat block: 128 rows x 1024 cols ----
        int pb = b - nWBlocks;                       // [0, 256)
        const int nPBlocks = (Prows / 128) * (K / 1024);   // 128
        const float* mat; float* o_;
        if (pb < nPBlocks) { mat = P;  o_ = g_pP;  }
        else               { mat = Ph; o_ = g_pPh; pb -= nPBlocks; }

        const int pColTiles = K / 1024;              // 2
        const int col = (pb % pColTiles) * 1024 + tid * 4;
        const int r0  = (pb / pColTiles) * 128;

        const float4* m  = reinterpret_cast<const float4*>(mat + (size_t)r0 * K + col);
        const float4* p4 = reinterpret_cast<const float4*>(pi + r0);
        const size_t  s4 = (size_t)K / 4;

        float4 acc = make_float4(0.f, 0.f, 0.f, 0.f);
        #pragma unroll 1
        for (int rr = 0; rr < 128; rr += 8) {
            float4 w0 = __ldg(m + 0 * s4);
            float4 w1 = __ldg(m + 1 * s4);
            float4 w2 = __ldg(m + 2 * s4);
            float4 w3 = __ldg(m + 3 * s4);
            float4 w4 = __ldg(m + 4 * s4);
            float4 w5 = __ldg(m + 5 * s4);
            float4 w6 = __ldg(m + 6 * s4);
            float4 w7 = __ldg(m + 7 * s4);
            float4 pa  = __ldg(p4 + 0);
            float4 pb2 = __ldg(p4 + 1);

            acc.x = fmaf(pa.x, w0.x, acc.x); acc.y = fmaf(pa.x, w0.y, acc.y);
            acc.z = fmaf(pa.x, w0.z, acc.z); acc.w = fmaf(pa.x, w0.w, acc.w);
            acc.x = fmaf(pa.y, w1.x, acc.x); acc.y = fmaf(pa.y, w1.y, acc.y);
            acc.z = fmaf(pa.y, w1.z, acc.z); acc.w = fmaf(pa.y, w1.w, acc.w);
            acc.x = fmaf(pa.z, w2.x, acc.x); acc.y = fmaf(pa.z, w2.y, acc.y);
            acc.z = fmaf(pa.z, w2.z, acc.z); acc.w = fmaf(pa.z, w2.w, acc.w);
            acc.x = fmaf(pa.w, w3.x, acc.x); acc.y = fmaf(pa.w, w3.y, acc.y);
            acc.z = fmaf(pa.w, w3.z, acc.z); acc.w = fmaf(pa.w, w3.w, acc.w);
            acc.x = fmaf(pb2.x, w4.x, acc.x); acc.y = fmaf(pb2.x, w4.y, acc.y);
            acc.z = fmaf(pb2.x, w4.z, acc.z); acc.w = fmaf(pb2.x, w4.w, acc.w);
            acc.x = fmaf(pb2.y, w5.x, acc.x); acc.y = fmaf(pb2.y, w5.y, acc.y);
            acc.z = fmaf(pb2.y, w5.z, acc.z); acc.w = fmaf(pb2.y, w5.w, acc.w);
            acc.x = fmaf(pb2.z, w6.x, acc.x); acc.y = fmaf(pb2.z, w6.y, acc.y);
            acc.z = fmaf(pb2.z, w6.z, acc.z); acc.w = fmaf(pb2.z, w6.w, acc.w);
            acc.x = fmaf(pb2.w, w7.x, acc.x); acc.y = fmaf(pb2.w, w7.y, acc.y);
            acc.z = fmaf(pb2.w, w7.z, acc.z); acc.w = fmaf(pb2.w, w7.w, acc.w);

            m  += 8 * s4;
            p4 += 2;
        }
        atomicAdd(&o_[col + 0], acc.x);
        atomicAdd(&o_[col + 1], acc.y);
        atomicAdd(&o_[col + 2], acc.z);
        atomicAdd(&o_[col + 3], acc.w);
    }

    // ---------------- signal matvec completion (race-safe) ----------------
    __syncthreads();               // all warps of this block done with stores
    __threadfence();
    if (tid == 0) atomicAdd(&g_done, 1u);
    if (b >= EPI_BLOCKS) return;

    // ======== epilogue blocks (b in [0, EPI_BLOCKS)) — light W blocks ======
    // Rank precompute (depends only on L/U) — runs while P blocks still
    // stream the bulk of the traffic.
    const int sliceLen   = (N + EPI_BLOCKS - 1) / EPI_BLOCKS;   // 64 @ N=4096
    const int sliceStart = b * sliceLen;

    int pre = 0;
    for (int i = tid; i < sliceStart; i += 256) {
        float li = __ldg(L + i), ui = __ldg(U + i);
        pre += (li < 0.0f && ui > 0.0f);
    }
    #pragma unroll
    for (int o = 16; o > 0; o >>= 1)
        pre += __shfl_down_sync(0xFFFFFFFFu, pre, o);
    __shared__ int wsum[8];
    __shared__ int wcnt[8];
    if (lane == 0) wsum[warp] = pre;
    if (tid < 8) wcnt[tid] = 0;
    __syncthreads();

    const int n = sliceStart + tid;          // one neuron per thread (tid<64)
    float l = 0.f, u = 0.f, c = 0.f;
    bool un = false;
    const bool active = (tid < sliceLen) && (n < N);
    if (active) {
        l = __ldg(L + n); u = __ldg(U + n); c = __ldg(C + n);
        un = (l < 0.0f) && (u > 0.0f);
    }
    unsigned bm = __ballot_sync(0xFFFFFFFFu, un);
    int before = __popc(bm & ((1u << lane) - 1u));
    if (lane == 0) wcnt[warp] = __popc(bm);
    __syncthreads();

    int prefix = 0;
    #pragma unroll
    for (int w = 0; w < 8; ++w) prefix += wsum[w];
    int woff = 0, totalCnt = 0;
    #pragma unroll
    for (int w = 0; w < 8; ++w) {
        woff     += (w < warp) ? wcnt[w] : 0;
        totalCnt += wcnt[w];
    }
    const int k = prefix + woff + before;
    float a_k = 0.0f;
    if (active && un && k < K) a_k = __ldg(alpha + k);

    // ---------------- wait for ALL blocks ----------------
    if (tid == 0) {
        while (atomicAdd(&g_done, 0u) < (unsigned)G) __nanosleep(32);
    }
    __syncthreads();
    __threadfence();

    // ---------------- elementwise epilogue (L2-hot) ----------------
    if (active) {
        float val;
        if (un) {
            if (k < K) {
                float vhat = g_sV[n] - g_pPh[k];
                float rp   = fmaxf(vhat, 0.0f);
                float rn   = fmaxf(-vhat, 0.0f);
                val = rp * u / (u - l) - c - a_k * rn - g_pP[k];
            } else {
                val = 0.0f;
            }
        } else if (u <= 0.0f) {
            val = -c;                  // stably deactivated (sV never needed)
        } else if (l >= 0.0f) {
            val = g_sV[n] - c;         // stably activated
        } else {
            val = 0.0f;
        }
        out[n] = val;
    }

    // ---------------- reset scratch for next graph replay ----------------
    __syncthreads();
    const int zEnd = (b == EPI_BLOCKS - 1) ? K : (prefix + totalCnt);
    for (int i = prefix + tid; i < zEnd; i += 256) {
        g_pP[i]  = 0.0f;
        g_pPh[i] = 0.0f;
    }
    __threadfence();
    if (tid == 0) {
        unsigned d2 = atomicAdd(&g_done2, 1u);
        if (d2 == EPI_BLOCKS - 1) {   // very last epilogue block resets counters
            g_done  = 0;
            g_done2 = 0;
            __threadfence();
        }
    }
}

extern "C" void kernel_launch(void* const* d_in, const int* in_sizes, int n_in,
                              void* d_out, int out_size) {
    const float* Vn    = (const float*)d_in[0];   // [N_NEXT]
    const float* W     = (const float*)d_in[1];   // [N_NEXT, N]
    const float* C     = (const float*)d_in[2];   // [N]
    const float* L     = (const float*)d_in[3];   // [N]
    const float* U     = (const float*)d_in[4];   // [N]
    const float* P     = (const float*)d_in[5];   // [P_ROWS, K]
    const float* Ph    = (const float*)d_in[6];   // [P_ROWS, K]
    const float* pi    = (const float*)d_in[7];   // [P_ROWS]
    const float* alpha = (const float*)d_in[8];   // [K]
    float* out = (float*)d_out;

    const int Nnext = in_sizes[0];
    const int N     = in_sizes[2];
    const int Prows = in_sizes[7];
    const int K     = in_sizes[8];

    // R4 layout: 512 W blocks + 2 * 128 P blocks = 768
    const int G = N / 8 + 2 * (Prows / 128) * (K / 1024);

    fused_kernel<<<G, 256>>>(W, Vn, P, Ph, pi, C, L, U, alpha, out,
                             N, Nnext, K, Prows, G);
}

// round 15
// speedup vs baseline: 1.3433x; 1.0241x over previous
#include <cuda_runtime.h>
#include <cuda_bf16.h>

// Scratch (device globals; zero-initialized at module load).
// g_sV: plain stores; stale entries only for rows with U<=0 (never read).
// g_pP/g_pPh: atomic accumulators, re-zeroed each run by epilogue blocks.
__device__ float g_sV[8192];
__device__ float g_pP[8192];
__device__ float g_pPh[8192];
__device__ unsigned g_done  = 0;
__device__ unsigned g_done2 = 0;

#define EPI_BLOCKS 64

// Single-launch fused kernel, heavy-first (LPT) ordering:
//   grid 768 x 256 threads, __launch_bounds__(256, 4) -> ~58 regs, full MLP.
//   blocks [0,256):   P/Ph block — 128 rows x 1024 cols (512KB), 256 thr x
//                     float4, 8-row load batches (MLP~10), atomicAdd partials.
//                     HEAVY blocks launch first -> start at t=0, define the
//                     makespan; fine-grained W blocks fill the tail.
//   blocks [256,768): W block — 8 contiguous rows, warp per row, 4096 cols,
//                     MLP~8; rows with U<=0 skipped (-16MB).
// Epilogue on blocks 0..63 (P blocks): they finish near the makespan, so the
// spin window is ~zero (R14 wasted ~10% of CTA slots on early-finishing
// W-block spinners). Rank precompute after own work, spin, L2-hot writes.
__global__ __launch_bounds__(256, 4)
void fused_kernel(const float* __restrict__ W,  const float* __restrict__ Vn,
                  const float* __restrict__ P,  const float* __restrict__ Ph,
                  const float* __restrict__ pi, const float* __restrict__ C,
                  const float* __restrict__ L,  const float* __restrict__ U,
                  const float* __restrict__ alpha, float* __restrict__ out,
                  int N, int Nnext, int K, int Prows, int G) {
    const int tid  = threadIdx.x;
    const int b    = blockIdx.x;
    const int lane = tid & 31;
    const int warp = tid >> 5;           // [0,8)

    const int nPBlocksTotal = 2 * (Prows / 128) * (K / 1024);   // 256

    if (b < nPBlocksTotal) {
        // ---- P / P_hat block: 128 rows x 1024 cols ----
        int pb = b;
        const int nPBlocks = nPBlocksTotal / 2;      // 128 per matrix
        const float* mat; float* o_;
        if (pb < nPBlocks) { mat = P;  o_ = g_pP;  }
        else               { mat = Ph; o_ = g_pPh; pb -= nPBlocks; }

        const int pColTiles = K / 1024;              // 2
        const int col = (pb % pColTiles) * 1024 + tid * 4;
        const int r0  = (pb / pColTiles) * 128;

        const float4* m  = reinterpret_cast<const float4*>(mat + (size_t)r0 * K + col);
        const float4* p4 = reinterpret_cast<const float4*>(pi + r0);
        const size_t  s4 = (size_t)K / 4;

        float4 acc = make_float4(0.f, 0.f, 0.f, 0.f);
        #pragma unroll 1
        for (int rr = 0; rr < 128; rr += 8) {
            float4 w0 = __ldg(m + 0 * s4);
            float4 w1 = __ldg(m + 1 * s4);
            float4 w2 = __ldg(m + 2 * s4);
            float4 w3 = __ldg(m + 3 * s4);
            float4 w4 = __ldg(m + 4 * s4);
            float4 w5 = __ldg(m + 5 * s4);
            float4 w6 = __ldg(m + 6 * s4);
            float4 w7 = __ldg(m + 7 * s4);
            float4 pa  = __ldg(p4 + 0);
            float4 pb2 = __ldg(p4 + 1);

            acc.x = fmaf(pa.x, w0.x, acc.x); acc.y = fmaf(pa.x, w0.y, acc.y);
            acc.z = fmaf(pa.x, w0.z, acc.z); acc.w = fmaf(pa.x, w0.w, acc.w);
            acc.x = fmaf(pa.y, w1.x, acc.x); acc.y = fmaf(pa.y, w1.y, acc.y);
            acc.z = fmaf(pa.y, w1.z, acc.z); acc.w = fmaf(pa.y, w1.w, acc.w);
            acc.x = fmaf(pa.z, w2.x, acc.x); acc.y = fmaf(pa.z, w2.y, acc.y);
            acc.z = fmaf(pa.z, w2.z, acc.z); acc.w = fmaf(pa.z, w2.w, acc.w);
            acc.x = fmaf(pa.w, w3.x, acc.x); acc.y = fmaf(pa.w, w3.y, acc.y);
            acc.z = fmaf(pa.w, w3.z, acc.z); acc.w = fmaf(pa.w, w3.w, acc.w);
            acc.x = fmaf(pb2.x, w4.x, acc.x); acc.y = fmaf(pb2.x, w4.y, acc.y);
            acc.z = fmaf(pb2.x, w4.z, acc.z); acc.w = fmaf(pb2.x, w4.w, acc.w);
            acc.x = fmaf(pb2.y, w5.x, acc.x); acc.y = fmaf(pb2.y, w5.y, acc.y);
            acc.z = fmaf(pb2.y, w5.z, acc.z); acc.w = fmaf(pb2.y, w5.w, acc.w);
            acc.x = fmaf(pb2.z, w6.x, acc.x); acc.y = fmaf(pb2.z, w6.y, acc.y);
            acc.z = fmaf(pb2.z, w6.z, acc.z); acc.w = fmaf(pb2.z, w6.w, acc.w);
            acc.x = fmaf(pb2.w, w7.x, acc.x); acc.y = fmaf(pb2.w, w7.y, acc.y);
            acc.z = fmaf(pb2.w, w7.z, acc.z); acc.w = fmaf(pb2.w, w7.w, acc.w);

            m  += 8 * s4;
            p4 += 2;
        }
        atomicAdd(&o_[col + 0], acc.x);
        atomicAdd(&o_[col + 1], acc.y);
        atomicAdd(&o_[col + 2], acc.z);
        atomicAdd(&o_[col + 3], acc.w);
    } else {
        // ---- W block: 8 contiguous rows, warp per row ----
        const int row = (b - nPBlocksTotal) * 8 + warp;

        if (__ldg(U + row) > 0.0f) {     // sV unused when U <= 0
            const float4* wr = reinterpret_cast<const float4*>(W + (size_t)row * Nnext) + lane;
            const float4* vv = reinterpret_cast<const float4*>(Vn) + lane;
            const int nBatch = Nnext / (32 * 4 * 4);      // 4096/512 = 8

            float acc = 0.0f;
            #pragma unroll 1
            for (int it = 0; it < nBatch; ++it) {
                float4 w0 = __ldg(wr + 0 * 32);
                float4 w1 = __ldg(wr + 1 * 32);
                float4 w2 = __ldg(wr + 2 * 32);
                float4 w3 = __ldg(wr + 3 * 32);
                float4 v0 = __ldg(vv + 0 * 32);
                float4 v1 = __ldg(vv + 1 * 32);
                float4 v2 = __ldg(vv + 2 * 32);
                float4 v3 = __ldg(vv + 3 * 32);
                acc = fmaf(w0.x, v0.x, acc); acc = fmaf(w0.y, v0.y, acc);
                acc = fmaf(w0.z, v0.z, acc); acc = fmaf(w0.w, v0.w, acc);
                acc = fmaf(w1.x, v1.x, acc); acc = fmaf(w1.y, v1.y, acc);
                acc = fmaf(w1.z, v1.z, acc); acc = fmaf(w1.w, v1.w, acc);
                acc = fmaf(w2.x, v2.x, acc); acc = fmaf(w2.y, v2.y, acc);
                acc = fmaf(w2.z, v2.z, acc); acc = fmaf(w2.w, v2.w, acc);
                acc = fmaf(w3.x, v3.x, acc); acc = fmaf(w3.y, v3.y, acc);
                acc = fmaf(w3.z, v3.z, acc); acc = fmaf(w3.w, v3.w, acc);
                wr += 4 * 32;
                vv += 4 * 32;
            }
            #pragma unroll
            for (int o = 16; o > 0; o >>= 1)
                acc += __shfl_down_sync(0xFFFFFFFFu, acc, o);
            if (lane == 0) g_sV[row] = acc;
        }
    }

    // ---------------- signal matvec completion (race-safe) ----------------
    __syncthreads();               // all warps of this block done with stores
    __threadfence();
    if (tid == 0) atomicAdd(&g_done, 1u);
    if (b >= EPI_BLOCKS) return;

    // ======== epilogue blocks (b in [0, EPI_BLOCKS)) — heavy P blocks ======
    // These finish near the makespan, so spin time is ~zero.
    const int sliceLen   = (N + EPI_BLOCKS - 1) / EPI_BLOCKS;   // 64 @ N=4096
    const int sliceStart = b * sliceLen;

    int pre = 0;
    for (int i = tid; i < sliceStart; i += 256) {
        float li = __ldg(L + i), ui = __ldg(U + i);
        pre += (li < 0.0f && ui > 0.0f);
    }
    #pragma unroll
    for (int o = 16; o > 0; o >>= 1)
        pre += __shfl_down_sync(0xFFFFFFFFu, pre, o);
    __shared__ int wsum[8];
    __shared__ int wcnt[8];
    if (lane == 0) wsum[warp] = pre;
    if (tid < 8) wcnt[tid] = 0;
    __syncthreads();

    const int n = sliceStart + tid;          // one neuron per thread (tid<64)
    float l = 0.f, u = 0.f, c = 0.f;
    bool un = false;
    const bool active = (tid < sliceLen) && (n < N);
    if (active) {
        l = __ldg(L + n); u = __ldg(U + n); c = __ldg(C + n);
        un = (l < 0.0f) && (u > 0.0f);
    }
    unsigned bm = __ballot_sync(0xFFFFFFFFu, un);
    int before = __popc(bm & ((1u << lane) - 1u));
    if (lane == 0) wcnt[warp] = __popc(bm);
    __syncthreads();

    int prefix = 0;
    #pragma unroll
    for (int w = 0; w < 8; ++w) prefix += wsum[w];
    int woff = 0, totalCnt = 0;
    #pragma unroll
    for (int w = 0; w < 8; ++w) {
        woff     += (w < warp) ? wcnt[w] : 0;
        totalCnt += wcnt[w];
    }
    const int k = prefix + woff + before;
    float a_k = 0.0f;
    if (active && un && k < K) a_k = __ldg(alpha + k);

    // ---------------- wait for ALL blocks ----------------
    if (tid == 0) {
        while (atomicAdd(&g_done, 0u) < (unsigned)G) __nanosleep(32);
    }
    __syncthreads();
    __threadfence();

    // ---------------- elementwise epilogue (L2-hot) ----------------
    if (active) {
        float val;
        if (un) {
            if (k < K) {
                float vhat = g_sV[n] - g_pPh[k];
                float rp   = fmaxf(vhat, 0.0f);
                float rn   = fmaxf(-vhat, 0.0f);
                val = rp * u / (u - l) - c - a_k * rn - g_pP[k];
            } else {
                val = 0.0f;
            }
        } else if (u <= 0.0f) {
            val = -c;                  // stably deactivated (sV never needed)
        } else if (l >= 0.0f) {
            val = g_sV[n] - c;         // stably activated
        } else {
            val = 0.0f;
        }
        out[n] = val;
    }

    // ---------------- reset scratch for next graph replay ----------------
    __syncthreads();
    const int zEnd = (b == EPI_BLOCKS - 1) ? K : (prefix + totalCnt);
    for (int i = prefix + tid; i < zEnd; i += 256) {
        g_pP[i]  = 0.0f;
        g_pPh[i] = 0.0f;
    }
    __threadfence();
    if (tid == 0) {
        unsigned d2 = atomicAdd(&g_done2, 1u);
        if (d2 == EPI_BLOCKS - 1) {   // very last epilogue block resets counters
            g_done  = 0;
            g_done2 = 0;
            __threadfence();
        }
    }
}

extern "C" void kernel_launch(void* const* d_in, const int* in_sizes, int n_in,
                              void* d_out, int out_size) {
    const float* Vn    = (const float*)d_in[0];   // [N_NEXT]
    const float* W     = (const float*)d_in[1];   // [N_NEXT, N]
    const float* C     = (const float*)d_in[2];   // [N]
    const float* L     = (const float*)d_in[3];   // [N]
    const float* U     = (const float*)d_in[4];   // [N]
    const float* P     = (const float*)d_in[5];   // [P_ROWS, K]
    const float* Ph    = (const float*)d_in[6];   // [P_ROWS, K]
    const float* pi    = (const float*)d_in[7];   // [P_ROWS]
    const float* alpha = (const float*)d_in[8];   // [K]
    float* out = (float*)d_out;

    const int Nnext = in_sizes[0];
    const int N     = in_sizes[2];
    const int Prows = in_sizes[7];
    const int K     = in_sizes[8];

    // Heavy-first layout: 256 P/Ph blocks then 512 W blocks = 768
    const int G = 2 * (Prows / 128) * (K / 1024) + N / 8;

    fused_kernel<<<G, 256>>>(W, Vn, P, Ph, pi, C, L, U, alpha, out,
                             N, Nnext, K, Prows, G);
}